// round 5
// baseline (speedup 1.0000x reference)
#include <cuda_runtime.h>
#include <math.h>

// DictionaryMatchingTv — bit-replicated fp32 nearest-atom search.
// R5: R3 worker structure (PX=1, no spills) + d2-grouping (fadd2 hoisted out
// of the hot loop -> 9 FMA-pipe ops per atom-pair).

#define MAX_D   4096
#define MAX_ETL 16
#define MAXG    64
#define NPB     256   // pixels per block
#define NG      4     // dictionary chunks (thread groups)
#define THREADS 1024

typedef unsigned long long ull;

__device__ int   g_cols[MAX_ETL];
__device__ int   g_ncols, g_kpad;

// K=8 grouped path
__device__ float g_vtmp[MAX_D * 8];
__device__ float g_d2a[MAX_D];
__device__ int   g_permAtom[MAX_D + 2 * MAXG];
__device__ float g_dbp[(MAX_D / 2 + MAXG) * 16];   // pair-interleaved
__device__ float g_d2p[MAX_D + 2 * MAXG];          // per-atom d2 (fallback)
__device__ int   g_idx[MAX_D + 2 * MAXG];          // permuted -> original index
__device__ int   g_gstartPair[MAXG + 1];
__device__ float g_gd2[MAXG];
__device__ int   g_ng, g_np, g_grouped;

// K=16 fallback path
__device__ float g_db16[MAX_D * MAX_ETL];
__device__ float g_d2_16[MAX_D];

// ---- packed f32x2 helpers (per-lane IEEE rn, identical to scalar) --------
__device__ __forceinline__ ull pack2(float lo, float hi) {
    ull r; asm("mov.b64 %0, {%1, %2};" : "=l"(r) : "f"(lo), "f"(hi)); return r;
}
__device__ __forceinline__ void unpack2(ull v, float& lo, float& hi) {
    asm("mov.b64 {%0, %1}, %2;" : "=f"(lo), "=f"(hi) : "l"(v));
}
__device__ __forceinline__ ull ffma2(ull a, ull b, ull c) {
    ull d; asm("fma.rn.f32x2 %0, %1, %2, %3;" : "=l"(d) : "l"(a), "l"(b), "l"(c)); return d;
}
__device__ __forceinline__ ull fadd2(ull a, ull b) {
    ull d; asm("add.rn.f32x2 %0, %1, %2;" : "=l"(d) : "l"(a), "l"(b)); return d;
}

// ---------------------------------------------------------------------------
// Prep: mask + normalize + d2-group + scatter pair-interleaved dict.
// (validated in R4: 1.27us, correct permutation/pad/merge semantics)
// ---------------------------------------------------------------------------
__global__ void __launch_bounds__(THREADS)
prep_kernel(const float* __restrict__ delta, const float* __restrict__ db_mag,
            int D, int etl) {
    const int tid = threadIdx.x;
    if (tid == 0) {
        int cnt = 0;
        for (int e = 0; e < etl && e < MAX_ETL; e++)
            if (__fmul_rn(delta[e], 1e-3f) < 1e-3f) g_cols[cnt++] = e;
        g_ncols = cnt;
        g_kpad  = (cnt <= 8) ? 8 : 16;
    }
    __syncthreads();
    const int ncols = g_ncols, kp = g_kpad;

    for (int d = tid; d < D; d += THREADS) {
        float x[MAX_ETL];
#pragma unroll
        for (int k = 0; k < MAX_ETL; k++)
            x[k] = (k < ncols) ? db_mag[d * etl + g_cols[k]] : 0.f;
        float ss = 0.f;
#pragma unroll
        for (int k = 0; k < MAX_ETL; k++) ss = __fadd_rn(ss, __fmul_rn(x[k], x[k]));
        const float nn = __fsqrt_rn(ss);
        float v[MAX_ETL]; float d2 = 0.f;
#pragma unroll
        for (int k = 0; k < MAX_ETL; k++) {
            v[k] = (nn > 0.f) ? __fdiv_rn(x[k], nn) : 0.f;
            d2 = __fadd_rn(d2, __fmul_rn(v[k], v[k]));
        }
        if (kp == 8) {
#pragma unroll
            for (int k = 0; k < 8; k++) g_vtmp[d * 8 + k] = v[k];
            g_d2a[d] = d2;
        } else {
#pragma unroll
            for (int k = 0; k < MAX_ETL; k++) g_db16[d * MAX_ETL + k] = v[k];
            g_d2_16[d] = d2;
        }
    }
    __syncthreads();
    if (kp != 8) return;

    __shared__ float s_dist[MAXG];
    __shared__ int   s_cnt[MAXG];
    __shared__ int   s_off[MAXG + 1];

    if (tid == 0) {
        int nd = 0; bool ok = true;
        for (int d = 0; d < D; d++) {
            const float vv = g_d2a[d];
            int gi = -1;
            for (int g = 0; g < nd; g++) if (s_dist[g] == vv) { gi = g; break; }
            if (gi < 0) {
                if (nd == MAXG) { ok = false; break; }
                s_dist[nd] = vv; s_cnt[nd] = 0; gi = nd++;
            }
            s_cnt[gi]++;
        }
        if (!ok) {
            g_grouped = 0;
            g_ng = 0;
            g_np = ((D + 1) & ~1) >> 1;
        } else {
            g_grouped = 1;
            s_off[0] = 0;
            for (int g = 0; g < nd; g++) s_off[g + 1] = s_off[g] + ((s_cnt[g] + 1) & ~1);
            int pos[MAXG];
            for (int g = 0; g < nd; g++) pos[g] = s_off[g];
            for (int d = 0; d < D; d++) {
                const float vv = g_d2a[d];
                int gi = 0; while (s_dist[gi] != vv) gi++;
                g_permAtom[pos[gi]++] = d;           // stable: ascending d in group
            }
            for (int g = 0; g < nd; g++)
                if (s_cnt[g] & 1)                     // pad = DUPLICATE of last atom
                    g_permAtom[s_off[g] + s_cnt[g]] = g_permAtom[s_off[g] + s_cnt[g] - 1];
            for (int g = 0; g < nd; g++) { g_gstartPair[g] = s_off[g] >> 1; g_gd2[g] = s_dist[g]; }
            g_gstartPair[nd] = s_off[nd] >> 1;
            g_ng = nd;
            g_np = s_off[nd] >> 1;
        }
    }
    __syncthreads();
    const int grouped = g_grouped;
    const int Dp = g_np * 2;
    for (int np = tid; np < Dp; np += THREADS) {
        const int d = grouped ? g_permAtom[np] : ((np < D) ? np : D - 1);
        const int base = (np >> 1) * 16 + (np & 1);
#pragma unroll
        for (int k = 0; k < 8; k++) g_dbp[base + 2 * k] = g_vtmp[d * 8 + k];
        g_idx[np] = d;
        g_d2p[np] = g_d2a[d];
    }
}

// ---------------------------------------------------------------------------
// Signal prep (two-stage normalization, exact fp32 replication).
// ---------------------------------------------------------------------------
template <int K>
__device__ __forceinline__ void prep_signal(const float* __restrict__ sig,
                                            int n, bool active, int etl,
                                            const int* s_cols, int ncols,
                                            float* v, float& s2) {
    float raw[MAX_ETL];
#pragma unroll
    for (int e = 0; e < MAX_ETL; e++)
        raw[e] = (active && e < etl) ? sig[n * etl + e] : 0.f;
    float ss1 = 0.f;
#pragma unroll
    for (int e = 0; e < MAX_ETL; e++) ss1 = __fadd_rn(ss1, __fmul_rn(raw[e], raw[e]));
    const float n1 = __fsqrt_rn(ss1);
    float t[K];
#pragma unroll
    for (int k = 0; k < K; k++) {
        t[k] = 0.f;
        if (k < ncols) t[k] = (n1 > 0.f) ? __fdiv_rn(raw[s_cols[k]], n1) : 0.f;
    }
    float ss2 = 0.f;
#pragma unroll
    for (int k = 0; k < K; k++) ss2 = __fadd_rn(ss2, __fmul_rn(t[k], t[k]));
    const float n2 = __fsqrt_rn(ss2);
#pragma unroll
    for (int k = 0; k < K; k++) v[k] = (n2 > 0.f) ? __fdiv_rn(t[k], n2) : 0.f;
    s2 = 0.f;
#pragma unroll
    for (int k = 0; k < K; k++) s2 = __fadd_rn(s2, __fmul_rn(v[k], v[k]));
}

// ---------------------------------------------------------------------------
// K=8 worker: 1024 thr = 256 pixels x 4 chunks. PX=1 (no spills).
// ---------------------------------------------------------------------------
__global__ void __launch_bounds__(THREADS, 1)
match8_kernel(const float* __restrict__ sig,
              const float* __restrict__ t2s,
              const float* __restrict__ b1s,
              float* __restrict__ out,
              int Npix, int D, int etl, int Pmax) {
    if (g_kpad != 8) return;

    extern __shared__ char smem_raw[];
    ull*   s_db  = (ull*)smem_raw;                           // Pmax*8 ull
    float* s_d2x = (float*)(smem_raw + (size_t)Pmax * 64);   // Pmax*2 (fallback)

    __shared__ float s_bu[NG * NPB];
    __shared__ int   s_bi[NG * NPB];
    __shared__ int   s_gstart[MAXG + 1];
    __shared__ ull   s_gd2p[MAXG];
    __shared__ int   s_cols[MAX_ETL];
    __shared__ int   s_ncols, s_np, s_ng, s_grouped;

    const int tid  = threadIdx.x;
    const int px   = tid & (NPB - 1);
    const int grp  = tid >> 8;            // 0..3

    if (tid < MAX_ETL) s_cols[tid] = g_cols[tid];
    if (tid == 0) { s_ncols = g_ncols; s_np = g_np; s_ng = g_ng; s_grouped = g_grouped; }
    {
        const int ngg = g_ng;
        if (tid <= ngg && tid <= MAXG) s_gstart[tid] = g_gstartPair[tid];
        if (tid < ngg) { const float dv = g_gd2[tid]; s_gd2p[tid] = pack2(dv, dv); }
    }
    __syncthreads();
    const int P = s_np;
    {
        const float4* src = (const float4*)g_dbp;
        float4* dst = (float4*)s_db;
        for (int i = tid; i < P * 4; i += THREADS) dst[i] = src[i];
        if (!s_grouped)
            for (int i = tid; i < P * 2; i += THREADS) s_d2x[i] = g_d2p[i];
    }

    const int n = blockIdx.x * NPB + px;
    const bool active = (n < Npix);

    float v[8]; float s2;
    prep_signal<8>(sig, n, active, etl, s_cols, s_ncols, v, s2);
    ull vk2[8];
#pragma unroll
    for (int k = 0; k < 8; k++) vk2[k] = pack2(v[k], v[k]);
    const ull s2p  = pack2(s2, s2);
    const ull neg2 = pack2(-2.f, -2.f);
    __syncthreads();

    const int Lp   = (P + NG - 1) / NG;
    const int myp0 = grp * Lp;
    const int myp1 = min(myp0 + Lp, P);

    float bU = INFINITY;
    int   bP = 0;

    if (s_grouped) {
        const int ng = s_ng;
        for (int g = 0; g < ng; g++) {
            const int a0 = max(s_gstart[g], myp0);
            const int a1 = min(s_gstart[g + 1], myp1);
            if (a0 >= a1) continue;
            const ull h = fadd2(s_gd2p[g], s2p);      // hoisted out of hot loop
            const ull* pp = s_db + (size_t)a0 * 8;
#pragma unroll 2
            for (int p = a0; p < a1; p++, pp += 8) {
                ull acc = 0ull;
#pragma unroll
                for (int k = 0; k < 8; k++) acc = ffma2(pp[k], vk2[k], acc);
                const ull u2 = ffma2(neg2, acc, h);   // exact: 2*dot unrounded
                float u0, u1; unpack2(u2, u0, u1);
                u0 = fmaxf(u0, 0.f);
                u1 = fmaxf(u1, 0.f);
                if (u0 < bU) { bU = u0; bP = 2 * p; }
                if (u1 < bU) { bU = u1; bP = 2 * p + 1; }
            }
        }
    } else {
        const ull* pp = s_db + (size_t)myp0 * 8;
#pragma unroll 2
        for (int p = myp0; p < myp1; p++, pp += 8) {
            ull acc = 0ull;
#pragma unroll
            for (int k = 0; k < 8; k++) acc = ffma2(pp[k], vk2[k], acc);
            const ull d2pair = *(const ull*)&s_d2x[2 * p];
            const ull h  = fadd2(d2pair, s2p);
            const ull u2 = ffma2(neg2, acc, h);
            float u0, u1; unpack2(u2, u0, u1);
            u0 = fmaxf(u0, 0.f);
            u1 = fmaxf(u1, 0.f);
            if (u0 < bU) { bU = u0; bP = 2 * p; }
            if (u1 < bU) { bU = u1; bP = 2 * p + 1; }
        }
    }

    const int bI = g_idx[bP];             // permuted -> original index
    s_bu[grp * NPB + px] = bU;
    s_bi[grp * NPB + px] = bI;
    __syncthreads();

    if (grp == 0 && active) {
        float bu = s_bu[px]; int bi = s_bi[px];
#pragma unroll
        for (int g = 1; g < NG; g++) {
            const float u = s_bu[g * NPB + px];
            const int   i = s_bi[g * NPB + px];
            if (u < bu || (u == bu && i < bi)) { bu = u; bi = i; }  // first-min
        }
        out[n]            = t2s[bi];
        out[Npix + n]     = b1s[bi];
        out[2 * Npix + n] = __fsqrt_rn(bu);
    }
}

// ---------------------------------------------------------------------------
// K=16 fallback (generic scalar, tiled).
// ---------------------------------------------------------------------------
__global__ void __launch_bounds__(256)
match16_kernel(const float* __restrict__ sig,
               const float* __restrict__ t2s,
               const float* __restrict__ b1s,
               float* __restrict__ out,
               int Npix, int D, int etl) {
    if (g_kpad != 16) return;
    constexpr int K = 16, TS = 512;
    __shared__ float4 s_db[TS * K / 4];
    __shared__ float  s_d2[TS];
    __shared__ int    s_cols[MAX_ETL];
    __shared__ int    s_ncols;

    const int tid = threadIdx.x;
    if (tid < MAX_ETL) s_cols[tid] = g_cols[tid];
    if (tid == 0) s_ncols = g_ncols;
    __syncthreads();
    const int n = blockIdx.x * blockDim.x + tid;
    const bool active = (n < Npix);

    float v[K]; float s2;
    prep_signal<K>(sig, n, active, etl, s_cols, s_ncols, v, s2);

    float bestU = INFINITY; int bestI = 0;
    for (int tile0 = 0; tile0 < D; tile0 += TS) {
        const int cnt = min(TS, D - tile0);
        __syncthreads();
        const float4* src = (const float4*)&g_db16[tile0 * K];
        for (int idx = tid; idx < cnt * K / 4; idx += blockDim.x) s_db[idx] = src[idx];
        for (int idx = tid; idx < cnt; idx += blockDim.x) s_d2[idx] = g_d2_16[tile0 + idx];
        __syncthreads();
        for (int aa = 0; aa < cnt; aa++) {
            const float4* p = &s_db[aa * (K / 4)];
            float dot = 0.f;
#pragma unroll
            for (int q = 0; q < K / 4; q++) {
                float4 w = p[q];
                dot = __fmaf_rn(w.x, v[4 * q + 0], dot);
                dot = __fmaf_rn(w.y, v[4 * q + 1], dot);
                dot = __fmaf_rn(w.z, v[4 * q + 2], dot);
                dot = __fmaf_rn(w.w, v[4 * q + 3], dot);
            }
            const float u = fmaxf(__fmaf_rn(-2.f, dot, __fadd_rn(s_d2[aa], s2)), 0.f);
            if (u < bestU) { bestU = u; bestI = tile0 + aa; }
        }
    }
    if (active) {
        out[n]            = t2s[bestI];
        out[Npix + n]     = b1s[bestI];
        out[2 * Npix + n] = __fsqrt_rn(bestU);
    }
}

// ---------------------------------------------------------------------------
extern "C" void kernel_launch(void* const* d_in, const int* in_sizes, int n_in,
                              void* d_out, int out_size) {
    const float* sig    = (const float*)d_in[0];
    const float* db_mag = (const float*)d_in[1];
    const float* t2s    = (const float*)d_in[2];
    const float* b1s    = (const float*)d_in[3];
    const float* delta  = (const float*)d_in[4];

    const int etl  = in_sizes[4];
    const int D    = in_sizes[1] / etl;
    const int Npix = in_sizes[0] / etl;
    float* out = (float*)d_out;

    const int Pmax = (D + 1) / 2 + MAXG;
    const size_t dyn = (size_t)Pmax * 64 + (size_t)Pmax * 8;
    cudaFuncSetAttribute(match8_kernel,
                         cudaFuncAttributeMaxDynamicSharedMemorySize, (int)dyn);

    prep_kernel<<<1, THREADS>>>(delta, db_mag, D, etl);
    match16_kernel<<<(Npix + 255) / 256, 256>>>(sig, t2s, b1s, out, Npix, D, etl);
    match8_kernel<<<(Npix + NPB - 1) / NPB, THREADS, dyn>>>(sig, t2s, b1s, out,
                                                           Npix, D, etl, Pmax);
}

// round 6
// speedup vs baseline: 1.0051x; 1.0051x over previous
#include <cuda_runtime.h>
#include <math.h>

// DictionaryMatchingTv — bit-replicated fp32 nearest-atom search.
// R6: one hot loop per kernel (grouped worker + ungrouped fallback as
// SEPARATE kernels) to avoid the R4/R5 register-pressure catastrophe.

#define MAX_D   4096
#define MAX_ETL 16
#define MAXG    64
#define NPB     256   // pixels per block
#define NG      4     // dictionary chunks (thread groups)
#define THREADS 1024

typedef unsigned long long ull;

__device__ int   g_cols[MAX_ETL];
__device__ int   g_ncols, g_kpad;

// K=8 path
__device__ float g_vtmp[MAX_D * 8];
__device__ float g_d2a[MAX_D];
__device__ int   g_permAtom[MAX_D + 2 * MAXG];
__device__ float g_dbp[(MAX_D / 2 + MAXG) * 16];   // pair-interleaved
__device__ float g_d2p[MAX_D + 2 * MAXG];          // per-atom d2 (fallback)
__device__ int   g_idx[MAX_D + 2 * MAXG];          // permuted -> original index
__device__ int   g_gstartPair[MAXG + 1];
__device__ float g_gd2[MAXG];
__device__ int   g_ng, g_np, g_grouped;

// K=16 fallback path
__device__ float g_db16[MAX_D * MAX_ETL];
__device__ float g_d2_16[MAX_D];

// ---- packed f32x2 helpers (per-lane IEEE rn, identical to scalar) --------
__device__ __forceinline__ ull pack2(float lo, float hi) {
    ull r; asm("mov.b64 %0, {%1, %2};" : "=l"(r) : "f"(lo), "f"(hi)); return r;
}
__device__ __forceinline__ void unpack2(ull v, float& lo, float& hi) {
    asm("mov.b64 {%0, %1}, %2;" : "=f"(lo), "=f"(hi) : "l"(v));
}
__device__ __forceinline__ ull ffma2(ull a, ull b, ull c) {
    ull d; asm("fma.rn.f32x2 %0, %1, %2, %3;" : "=l"(d) : "l"(a), "l"(b), "l"(c)); return d;
}
__device__ __forceinline__ ull fadd2(ull a, ull b) {
    ull d; asm("add.rn.f32x2 %0, %1, %2;" : "=l"(d) : "l"(a), "l"(b)); return d;
}

// ---------------------------------------------------------------------------
// Prep (validated R4/R5): mask + normalize + d2-group + pair-interleave.
// ---------------------------------------------------------------------------
__global__ void __launch_bounds__(THREADS)
prep_kernel(const float* __restrict__ delta, const float* __restrict__ db_mag,
            int D, int etl) {
    const int tid = threadIdx.x;
    if (tid == 0) {
        int cnt = 0;
        for (int e = 0; e < etl && e < MAX_ETL; e++)
            if (__fmul_rn(delta[e], 1e-3f) < 1e-3f) g_cols[cnt++] = e;
        g_ncols = cnt;
        g_kpad  = (cnt <= 8) ? 8 : 16;
    }
    __syncthreads();
    const int ncols = g_ncols, kp = g_kpad;

    for (int d = tid; d < D; d += THREADS) {
        float x[MAX_ETL];
#pragma unroll
        for (int k = 0; k < MAX_ETL; k++)
            x[k] = (k < ncols) ? db_mag[d * etl + g_cols[k]] : 0.f;
        float ss = 0.f;
#pragma unroll
        for (int k = 0; k < MAX_ETL; k++) ss = __fadd_rn(ss, __fmul_rn(x[k], x[k]));
        const float nn = __fsqrt_rn(ss);
        float v[MAX_ETL]; float d2 = 0.f;
#pragma unroll
        for (int k = 0; k < MAX_ETL; k++) {
            v[k] = (nn > 0.f) ? __fdiv_rn(x[k], nn) : 0.f;
            d2 = __fadd_rn(d2, __fmul_rn(v[k], v[k]));
        }
        if (kp == 8) {
#pragma unroll
            for (int k = 0; k < 8; k++) g_vtmp[d * 8 + k] = v[k];
            g_d2a[d] = d2;
        } else {
#pragma unroll
            for (int k = 0; k < MAX_ETL; k++) g_db16[d * MAX_ETL + k] = v[k];
            g_d2_16[d] = d2;
        }
    }
    __syncthreads();
    if (kp != 8) return;

    __shared__ float s_dist[MAXG];
    __shared__ int   s_cnt[MAXG];
    __shared__ int   s_off[MAXG + 1];

    if (tid == 0) {
        int nd = 0; bool ok = true;
        for (int d = 0; d < D; d++) {
            const float vv = g_d2a[d];
            int gi = -1;
            for (int g = 0; g < nd; g++) if (s_dist[g] == vv) { gi = g; break; }
            if (gi < 0) {
                if (nd == MAXG) { ok = false; break; }
                s_dist[nd] = vv; s_cnt[nd] = 0; gi = nd++;
            }
            s_cnt[gi]++;
        }
        if (!ok) {
            g_grouped = 0;
            g_ng = 0;
            g_np = ((D + 1) & ~1) >> 1;
        } else {
            g_grouped = 1;
            s_off[0] = 0;
            for (int g = 0; g < nd; g++) s_off[g + 1] = s_off[g] + ((s_cnt[g] + 1) & ~1);
            int pos[MAXG];
            for (int g = 0; g < nd; g++) pos[g] = s_off[g];
            for (int d = 0; d < D; d++) {
                const float vv = g_d2a[d];
                int gi = 0; while (s_dist[gi] != vv) gi++;
                g_permAtom[pos[gi]++] = d;           // stable: ascending d in group
            }
            for (int g = 0; g < nd; g++)
                if (s_cnt[g] & 1)                     // pad = DUPLICATE of last atom
                    g_permAtom[s_off[g] + s_cnt[g]] = g_permAtom[s_off[g] + s_cnt[g] - 1];
            for (int g = 0; g < nd; g++) { g_gstartPair[g] = s_off[g] >> 1; g_gd2[g] = s_dist[g]; }
            g_gstartPair[nd] = s_off[nd] >> 1;
            g_ng = nd;
            g_np = s_off[nd] >> 1;
        }
    }
    __syncthreads();
    const int grouped = g_grouped;
    const int Dp = g_np * 2;
    for (int np = tid; np < Dp; np += THREADS) {
        const int d = grouped ? g_permAtom[np] : ((np < D) ? np : D - 1);
        const int base = (np >> 1) * 16 + (np & 1);
#pragma unroll
        for (int k = 0; k < 8; k++) g_dbp[base + 2 * k] = g_vtmp[d * 8 + k];
        g_idx[np] = d;
        g_d2p[np] = g_d2a[d];
    }
}

// ---------------------------------------------------------------------------
// Signal prep (two-stage normalization, exact fp32 replication).
// ---------------------------------------------------------------------------
template <int K>
__device__ __forceinline__ void prep_signal(const float* __restrict__ sig,
                                            int n, bool active, int etl,
                                            const int* s_cols, int ncols,
                                            float* v, float& s2) {
    float raw[MAX_ETL];
#pragma unroll
    for (int e = 0; e < MAX_ETL; e++)
        raw[e] = (active && e < etl) ? sig[n * etl + e] : 0.f;
    float ss1 = 0.f;
#pragma unroll
    for (int e = 0; e < MAX_ETL; e++) ss1 = __fadd_rn(ss1, __fmul_rn(raw[e], raw[e]));
    const float n1 = __fsqrt_rn(ss1);
    float t[K];
#pragma unroll
    for (int k = 0; k < K; k++) {
        t[k] = 0.f;
        if (k < ncols) t[k] = (n1 > 0.f) ? __fdiv_rn(raw[s_cols[k]], n1) : 0.f;
    }
    float ss2 = 0.f;
#pragma unroll
    for (int k = 0; k < K; k++) ss2 = __fadd_rn(ss2, __fmul_rn(t[k], t[k]));
    const float n2 = __fsqrt_rn(ss2);
#pragma unroll
    for (int k = 0; k < K; k++) v[k] = (n2 > 0.f) ? __fdiv_rn(t[k], n2) : 0.f;
    s2 = 0.f;
#pragma unroll
    for (int k = 0; k < K; k++) s2 = __fadd_rn(s2, __fmul_rn(v[k], v[k]));
}

// ---------------------------------------------------------------------------
// Worker epilogue shared by both match8 kernels.
// ---------------------------------------------------------------------------
__device__ __forceinline__ void merge_and_store(
        float* s_bu, int* s_bi, int grp, int px, bool active, int n,
        const float* __restrict__ t2s, const float* __restrict__ b1s,
        float* __restrict__ out, int Npix, float bU, int bI) {
    s_bu[grp * NPB + px] = bU;
    s_bi[grp * NPB + px] = bI;
    __syncthreads();
    if (grp == 0 && active) {
        float bu = s_bu[px]; int bi = s_bi[px];
#pragma unroll
        for (int g = 1; g < NG; g++) {
            const float u = s_bu[g * NPB + px];
            const int   i = s_bi[g * NPB + px];
            if (u < bu || (u == bu && i < bi)) { bu = u; bi = i; }  // first-min
        }
        out[n]            = t2s[bi];
        out[Npix + n]     = b1s[bi];
        out[2 * Npix + n] = __fsqrt_rn(bu);
    }
}

// ---------------------------------------------------------------------------
// K=8 GROUPED worker (only hot loop in this kernel): 9 FMA ops/pair.
// ---------------------------------------------------------------------------
__global__ void __launch_bounds__(THREADS, 1)
match8g_kernel(const float* __restrict__ sig,
               const float* __restrict__ t2s,
               const float* __restrict__ b1s,
               float* __restrict__ out,
               int Npix, int D, int etl, int Pmax) {
    if (g_kpad != 8 || !g_grouped) return;

    extern __shared__ char smem_raw[];
    ull* s_db = (ull*)smem_raw;                     // Pmax*8 ull

    __shared__ float s_bu[NG * NPB];
    __shared__ int   s_bi[NG * NPB];
    __shared__ int   s_gstart[MAXG + 1];
    __shared__ ull   s_gd2p[MAXG];
    __shared__ int   s_cols[MAX_ETL];
    __shared__ int   s_ncols, s_np, s_ng;

    const int tid = threadIdx.x;
    const int px  = tid & (NPB - 1);
    const int grp = tid >> 8;

    if (tid < MAX_ETL) s_cols[tid] = g_cols[tid];
    if (tid == 0) { s_ncols = g_ncols; s_np = g_np; s_ng = g_ng; }
    {
        const int ngg = g_ng;
        if (tid <= ngg && tid <= MAXG) s_gstart[tid] = g_gstartPair[tid];
        if (tid < ngg) { const float dv = g_gd2[tid]; s_gd2p[tid] = pack2(dv, dv); }
    }
    __syncthreads();
    const int P = s_np;
    {
        const float4* src = (const float4*)g_dbp;
        float4* dst = (float4*)s_db;
        for (int i = tid; i < P * 4; i += THREADS) dst[i] = src[i];
    }

    const int n = blockIdx.x * NPB + px;
    const bool active = (n < Npix);

    float v[8]; float s2;
    prep_signal<8>(sig, n, active, etl, s_cols, s_ncols, v, s2);
    ull vk2[8];
#pragma unroll
    for (int k = 0; k < 8; k++) vk2[k] = pack2(v[k], v[k]);
    const ull s2p  = pack2(s2, s2);
    const ull neg2 = pack2(-2.f, -2.f);
    __syncthreads();

    const int Lp   = (P + NG - 1) / NG;
    const int myp0 = grp * Lp;
    const int myp1 = min(myp0 + Lp, P);

    float bU = INFINITY;
    int   bP = 0;

    const int ng = s_ng;
    for (int g = 0; g < ng; g++) {
        const int a0 = max(s_gstart[g], myp0);
        const int a1 = min(s_gstart[g + 1], myp1);
        if (a0 >= a1) continue;
        const ull h = fadd2(s_gd2p[g], s2p);        // hoisted per group
        const ull* pp = s_db + (size_t)a0 * 8;
#pragma unroll 2
        for (int p = a0; p < a1; p++, pp += 8) {
            ull acc = 0ull;
#pragma unroll
            for (int k = 0; k < 8; k++) acc = ffma2(pp[k], vk2[k], acc);
            const ull u2 = ffma2(neg2, acc, h);     // exact: 2*dot unrounded
            float u0, u1; unpack2(u2, u0, u1);
            u0 = fmaxf(u0, 0.f);
            u1 = fmaxf(u1, 0.f);
            if (u0 < bU) { bU = u0; bP = 2 * p; }
            if (u1 < bU) { bU = u1; bP = 2 * p + 1; }
        }
    }

    merge_and_store(s_bu, s_bi, grp, px, active, n, t2s, b1s, out, Npix,
                    bU, g_idx[bP]);
}

// ---------------------------------------------------------------------------
// K=8 UNGROUPED fallback — exact R3 hot loop (proven 95us), own kernel.
// ---------------------------------------------------------------------------
__global__ void __launch_bounds__(THREADS, 1)
match8u_kernel(const float* __restrict__ sig,
               const float* __restrict__ t2s,
               const float* __restrict__ b1s,
               float* __restrict__ out,
               int Npix, int D, int etl, int Pmax) {
    if (g_kpad != 8 || g_grouped) return;

    extern __shared__ char smem_raw[];
    ull*   s_db  = (ull*)smem_raw;
    float* s_d2x = (float*)(smem_raw + (size_t)Pmax * 64);

    __shared__ float s_bu[NG * NPB];
    __shared__ int   s_bi[NG * NPB];
    __shared__ int   s_cols[MAX_ETL];
    __shared__ int   s_ncols, s_np;

    const int tid = threadIdx.x;
    const int px  = tid & (NPB - 1);
    const int grp = tid >> 8;

    if (tid < MAX_ETL) s_cols[tid] = g_cols[tid];
    if (tid == 0) { s_ncols = g_ncols; s_np = g_np; }
    __syncthreads();
    const int P = s_np;
    {
        const float4* src = (const float4*)g_dbp;
        float4* dst = (float4*)s_db;
        for (int i = tid; i < P * 4; i += THREADS) dst[i] = src[i];
        for (int i = tid; i < P * 2; i += THREADS) s_d2x[i] = g_d2p[i];
    }

    const int n = blockIdx.x * NPB + px;
    const bool active = (n < Npix);

    float v[8]; float s2;
    prep_signal<8>(sig, n, active, etl, s_cols, s_ncols, v, s2);
    ull vk2[8];
#pragma unroll
    for (int k = 0; k < 8; k++) vk2[k] = pack2(v[k], v[k]);
    const ull s2p  = pack2(s2, s2);
    const ull neg2 = pack2(-2.f, -2.f);
    __syncthreads();

    const int Lp   = (P + NG - 1) / NG;
    const int myp0 = grp * Lp;
    const int myp1 = min(myp0 + Lp, P);

    float bU = INFINITY;
    int   bP = 0;

    const ull* pp = s_db + (size_t)myp0 * 8;
#pragma unroll 2
    for (int p = myp0; p < myp1; p++, pp += 8) {
        ull acc = 0ull;
#pragma unroll
        for (int k = 0; k < 8; k++) acc = ffma2(pp[k], vk2[k], acc);
        const ull d2pair = *(const ull*)&s_d2x[2 * p];
        const ull h  = fadd2(d2pair, s2p);
        const ull u2 = ffma2(neg2, acc, h);
        float u0, u1; unpack2(u2, u0, u1);
        u0 = fmaxf(u0, 0.f);
        u1 = fmaxf(u1, 0.f);
        if (u0 < bU) { bU = u0; bP = 2 * p; }
        if (u1 < bU) { bU = u1; bP = 2 * p + 1; }
    }

    merge_and_store(s_bu, s_bi, grp, px, active, n, t2s, b1s, out, Npix,
                    bU, g_idx[bP]);
}

// ---------------------------------------------------------------------------
// K=16 fallback (generic scalar, tiled).
// ---------------------------------------------------------------------------
__global__ void __launch_bounds__(256)
match16_kernel(const float* __restrict__ sig,
               const float* __restrict__ t2s,
               const float* __restrict__ b1s,
               float* __restrict__ out,
               int Npix, int D, int etl) {
    if (g_kpad != 16) return;
    constexpr int K = 16, TS = 512;
    __shared__ float4 s_db[TS * K / 4];
    __shared__ float  s_d2[TS];
    __shared__ int    s_cols[MAX_ETL];
    __shared__ int    s_ncols;

    const int tid = threadIdx.x;
    if (tid < MAX_ETL) s_cols[tid] = g_cols[tid];
    if (tid == 0) s_ncols = g_ncols;
    __syncthreads();
    const int n = blockIdx.x * blockDim.x + tid;
    const bool active = (n < Npix);

    float v[K]; float s2;
    prep_signal<K>(sig, n, active, etl, s_cols, s_ncols, v, s2);

    float bestU = INFINITY; int bestI = 0;
    for (int tile0 = 0; tile0 < D; tile0 += TS) {
        const int cnt = min(TS, D - tile0);
        __syncthreads();
        const float4* src = (const float4*)&g_db16[tile0 * K];
        for (int idx = tid; idx < cnt * K / 4; idx += blockDim.x) s_db[idx] = src[idx];
        for (int idx = tid; idx < cnt; idx += blockDim.x) s_d2[idx] = g_d2_16[tile0 + idx];
        __syncthreads();
        for (int aa = 0; aa < cnt; aa++) {
            const float4* p = &s_db[aa * (K / 4)];
            float dot = 0.f;
#pragma unroll
            for (int q = 0; q < K / 4; q++) {
                float4 w = p[q];
                dot = __fmaf_rn(w.x, v[4 * q + 0], dot);
                dot = __fmaf_rn(w.y, v[4 * q + 1], dot);
                dot = __fmaf_rn(w.z, v[4 * q + 2], dot);
                dot = __fmaf_rn(w.w, v[4 * q + 3], dot);
            }
            const float u = fmaxf(__fmaf_rn(-2.f, dot, __fadd_rn(s_d2[aa], s2)), 0.f);
            if (u < bestU) { bestU = u; bestI = tile0 + aa; }
        }
    }
    if (active) {
        out[n]            = t2s[bestI];
        out[Npix + n]     = b1s[bestI];
        out[2 * Npix + n] = __fsqrt_rn(bestU);
    }
}

// ---------------------------------------------------------------------------
extern "C" void kernel_launch(void* const* d_in, const int* in_sizes, int n_in,
                              void* d_out, int out_size) {
    const float* sig    = (const float*)d_in[0];
    const float* db_mag = (const float*)d_in[1];
    const float* t2s    = (const float*)d_in[2];
    const float* b1s    = (const float*)d_in[3];
    const float* delta  = (const float*)d_in[4];

    const int etl  = in_sizes[4];
    const int D    = in_sizes[1] / etl;
    const int Npix = in_sizes[0] / etl;
    float* out = (float*)d_out;

    const int Pmax = (D + 1) / 2 + MAXG;
    const size_t dyn = (size_t)Pmax * 64 + (size_t)Pmax * 8;
    cudaFuncSetAttribute(match8g_kernel,
                         cudaFuncAttributeMaxDynamicSharedMemorySize, (int)dyn);
    cudaFuncSetAttribute(match8u_kernel,
                         cudaFuncAttributeMaxDynamicSharedMemorySize, (int)dyn);

    const int grid8 = (Npix + NPB - 1) / NPB;
    prep_kernel<<<1, THREADS>>>(delta, db_mag, D, etl);
    match8g_kernel<<<grid8, THREADS, dyn>>>(sig, t2s, b1s, out, Npix, D, etl, Pmax);
    match8u_kernel<<<grid8, THREADS, dyn>>>(sig, t2s, b1s, out, Npix, D, etl, Pmax);
    match16_kernel<<<(Npix + 255) / 256, 256>>>(sig, t2s, b1s, out, Npix, D, etl);
}

// round 7
// speedup vs baseline: 13.7758x; 13.7065x over previous
#include <cuda_runtime.h>
#include <math.h>

// DictionaryMatchingTv — bit-replicated fp32 nearest-atom search.
// R7: revert to proven R3 structure. Parallel-only prep (NO serial grouping —
// that was the R4-R6 1.3ms regression). R3-exact FFMA2 hot loop.

#define MAX_D   4096
#define MAX_ETL 16
#define NPB     256   // pixels per block
#define NG      4     // dictionary chunks (thread groups)
#define THREADS 1024

typedef unsigned long long ull;

__device__ int   g_cols[MAX_ETL];
__device__ int   g_ncols, g_kpad;

// K=8 path: pair-interleaved dict (a0k,a1k per k), flat d2 per atom (padded)
__device__ float g_dbp[((MAX_D + 1) / 2) * 16];
__device__ float g_d2p[MAX_D + 1];

// K=16 fallback path
__device__ float g_db16[MAX_D * MAX_ETL];
__device__ float g_d2_16[MAX_D];

// ---- packed f32x2 helpers (per-lane IEEE rn, identical to scalar) --------
__device__ __forceinline__ ull pack2(float lo, float hi) {
    ull r; asm("mov.b64 %0, {%1, %2};" : "=l"(r) : "f"(lo), "f"(hi)); return r;
}
__device__ __forceinline__ void unpack2(ull v, float& lo, float& hi) {
    asm("mov.b64 {%0, %1}, %2;" : "=f"(lo), "=f"(hi) : "l"(v));
}
__device__ __forceinline__ ull ffma2(ull a, ull b, ull c) {
    ull d; asm("fma.rn.f32x2 %0, %1, %2, %3;" : "=l"(d) : "l"(a), "l"(b), "l"(c)); return d;
}
__device__ __forceinline__ ull fadd2(ull a, ull b) {
    ull d; asm("add.rn.f32x2 %0, %1, %2;" : "=l"(d) : "l"(a), "l"(b)); return d;
}

// ---------------------------------------------------------------------------
// Prep: fully parallel. Each block recomputes the mask locally (deterministic),
// then each thread normalizes one atom and scatters it.
// ---------------------------------------------------------------------------
__global__ void __launch_bounds__(128)
prep_kernel(const float* __restrict__ delta, const float* __restrict__ db_mag,
            int D, int etl) {
    __shared__ int s_cols[MAX_ETL];
    __shared__ int s_ncols;
    if (threadIdx.x == 0) {
        int cnt = 0;
        for (int e = 0; e < etl && e < MAX_ETL; e++)
            if (__fmul_rn(delta[e], 1e-3f) < 1e-3f) s_cols[cnt++] = e;
        s_ncols = cnt;
        if (blockIdx.x == 0) {
            for (int k = 0; k < cnt; k++) g_cols[k] = s_cols[k];
            g_ncols = cnt;
            g_kpad  = (cnt <= 8) ? 8 : 16;
        }
    }
    __syncthreads();
    const int ncols = s_ncols;
    const int kp    = (ncols <= 8) ? 8 : 16;
    const int Dpad  = (D + 1) & ~1;

    for (int a = blockIdx.x * blockDim.x + threadIdx.x; a < Dpad;
         a += gridDim.x * blockDim.x) {
        const int d = (a < D) ? a : D - 1;          // pad = duplicate last atom
        float x[MAX_ETL];
#pragma unroll
        for (int k = 0; k < MAX_ETL; k++)
            x[k] = (k < ncols) ? db_mag[d * etl + s_cols[k]] : 0.f;
        float ss = 0.f;
#pragma unroll
        for (int k = 0; k < MAX_ETL; k++) ss = __fadd_rn(ss, __fmul_rn(x[k], x[k]));
        const float nn = __fsqrt_rn(ss);
        float v[MAX_ETL]; float d2 = 0.f;
#pragma unroll
        for (int k = 0; k < MAX_ETL; k++) {
            v[k] = (nn > 0.f) ? __fdiv_rn(x[k], nn) : 0.f;
            d2 = __fadd_rn(d2, __fmul_rn(v[k], v[k]));
        }
        if (kp == 8) {
            const int base = (a >> 1) * 16 + (a & 1);
#pragma unroll
            for (int k = 0; k < 8; k++) g_dbp[base + 2 * k] = v[k];
            g_d2p[a] = d2;
        } else if (a < D) {
#pragma unroll
            for (int k = 0; k < MAX_ETL; k++) g_db16[d * MAX_ETL + k] = v[k];
            g_d2_16[d] = d2;
        }
    }
}

// ---------------------------------------------------------------------------
// Signal prep (two-stage normalization, exact fp32 replication).
// ---------------------------------------------------------------------------
template <int K>
__device__ __forceinline__ void prep_signal(const float* __restrict__ sig,
                                            int n, bool active, int etl,
                                            const int* s_cols, int ncols,
                                            float* v, float& s2) {
    float raw[MAX_ETL];
#pragma unroll
    for (int e = 0; e < MAX_ETL; e++)
        raw[e] = (active && e < etl) ? sig[n * etl + e] : 0.f;
    float ss1 = 0.f;
#pragma unroll
    for (int e = 0; e < MAX_ETL; e++) ss1 = __fadd_rn(ss1, __fmul_rn(raw[e], raw[e]));
    const float n1 = __fsqrt_rn(ss1);
    float t[K];
#pragma unroll
    for (int k = 0; k < K; k++) {
        t[k] = 0.f;
        if (k < ncols) t[k] = (n1 > 0.f) ? __fdiv_rn(raw[s_cols[k]], n1) : 0.f;
    }
    float ss2 = 0.f;
#pragma unroll
    for (int k = 0; k < K; k++) ss2 = __fadd_rn(ss2, __fmul_rn(t[k], t[k]));
    const float n2 = __fsqrt_rn(ss2);
#pragma unroll
    for (int k = 0; k < K; k++) v[k] = (n2 > 0.f) ? __fdiv_rn(t[k], n2) : 0.f;
    s2 = 0.f;
#pragma unroll
    for (int k = 0; k < K; k++) s2 = __fadd_rn(s2, __fmul_rn(v[k], v[k]));
}

// ---------------------------------------------------------------------------
// K=8 worker (R3-exact): 1024 thr = 256 pixels x 4 pair-chunks.
// ---------------------------------------------------------------------------
__global__ void __launch_bounds__(THREADS, 1)
match8_kernel(const float* __restrict__ sig,
              const float* __restrict__ t2s,
              const float* __restrict__ b1s,
              float* __restrict__ out,
              int Npix, int D, int etl) {
    if (g_kpad != 8) return;

    const int P = (D + 1) >> 1;             // atom pairs (padded)
    extern __shared__ char smem_raw[];
    float* s_db = (float*)smem_raw;         // P*16 floats, pair-interleaved
    float* s_d2 = s_db + P * 16;            // 2*P floats (8B-aligned: P*16 even)
    float* s_bu = s_d2 + 2 * P;
    int*   s_bi = (int*)(s_bu + NG * NPB);

    __shared__ int s_cols[MAX_ETL];
    __shared__ int s_ncols;

    const int tid = threadIdx.x;
    const int px  = tid & (NPB - 1);
    const int grp = tid >> 8;               // 0..3

    if (tid < MAX_ETL) s_cols[tid] = g_cols[tid];
    if (tid == 0) s_ncols = g_ncols;
    {
        const float4* src = (const float4*)g_dbp;
        float4* dst = (float4*)s_db;
        for (int i = tid; i < P * 4; i += THREADS) dst[i] = src[i];
        for (int i = tid; i < 2 * P; i += THREADS) s_d2[i] = g_d2p[i];
    }
    __syncthreads();

    const int n = blockIdx.x * NPB + px;
    const bool active = (n < Npix);

    float v[8]; float s2;
    prep_signal<8>(sig, n, active, etl, s_cols, s_ncols, v, s2);
    ull vk2[8];
#pragma unroll
    for (int k = 0; k < 8; k++) vk2[k] = pack2(v[k], v[k]);
    const ull s2p  = pack2(s2, s2);
    const ull neg2 = pack2(-2.f, -2.f);
    __syncthreads();

    const int Lp   = (P + NG - 1) / NG;
    const int myp0 = grp * Lp;
    const int myp1 = min(myp0 + Lp, P);

    float bU = INFINITY;
    int   bA = 0;

    const ull* pp = (const ull*)s_db + (size_t)myp0 * 8;
#pragma unroll 2
    for (int p = myp0; p < myp1; p++, pp += 8) {
        ull acc = 0ull;
#pragma unroll
        for (int k = 0; k < 8; k++) acc = ffma2(pp[k], vk2[k], acc);
        const ull d2pair = *(const ull*)&s_d2[2 * p];
        const ull h  = fadd2(d2pair, s2p);
        const ull u2 = ffma2(neg2, acc, h);     // exact: 2*dot unrounded
        float u0, u1; unpack2(u2, u0, u1);
        u0 = fmaxf(u0, 0.f);
        u1 = fmaxf(u1, 0.f);
        if (u0 < bU) { bU = u0; bA = 2 * p; }   // strict < -> first minimum
        if (u1 < bU) { bU = u1; bA = 2 * p + 1; }
    }
    if (bA >= D) bA = D - 1;                    // pad lane = duplicate of last

    s_bu[grp * NPB + px] = bU;
    s_bi[grp * NPB + px] = bA;
    __syncthreads();

    if (grp == 0 && active) {
        float bu = s_bu[px]; int bi = s_bi[px];
#pragma unroll
        for (int g = 1; g < NG; g++) {
            const float u = s_bu[g * NPB + px];
            const int   i = s_bi[g * NPB + px];
            if (u < bu || (u == bu && i < bi)) { bu = u; bi = i; }  // first-min
        }
        out[n]            = t2s[bi];
        out[Npix + n]     = b1s[bi];
        out[2 * Npix + n] = __fsqrt_rn(bu);
    }
}

// ---------------------------------------------------------------------------
// K=16 fallback (generic scalar, tiled).
// ---------------------------------------------------------------------------
__global__ void __launch_bounds__(256)
match16_kernel(const float* __restrict__ sig,
               const float* __restrict__ t2s,
               const float* __restrict__ b1s,
               float* __restrict__ out,
               int Npix, int D, int etl) {
    if (g_kpad != 16) return;
    constexpr int K = 16, TS = 512;
    __shared__ float4 s_db[TS * K / 4];
    __shared__ float  s_d2[TS];
    __shared__ int    s_cols[MAX_ETL];
    __shared__ int    s_ncols;

    const int tid = threadIdx.x;
    if (tid < MAX_ETL) s_cols[tid] = g_cols[tid];
    if (tid == 0) s_ncols = g_ncols;
    __syncthreads();
    const int n = blockIdx.x * blockDim.x + tid;
    const bool active = (n < Npix);

    float v[K]; float s2;
    prep_signal<K>(sig, n, active, etl, s_cols, s_ncols, v, s2);

    float bestU = INFINITY; int bestI = 0;
    for (int tile0 = 0; tile0 < D; tile0 += TS) {
        const int cnt = min(TS, D - tile0);
        __syncthreads();
        const float4* src = (const float4*)&g_db16[tile0 * K];
        for (int idx = tid; idx < cnt * K / 4; idx += blockDim.x) s_db[idx] = src[idx];
        for (int idx = tid; idx < cnt; idx += blockDim.x) s_d2[idx] = g_d2_16[tile0 + idx];
        __syncthreads();
        for (int aa = 0; aa < cnt; aa++) {
            const float4* p = &s_db[aa * (K / 4)];
            float dot = 0.f;
#pragma unroll
            for (int q = 0; q < K / 4; q++) {
                float4 w = p[q];
                dot = __fmaf_rn(w.x, v[4 * q + 0], dot);
                dot = __fmaf_rn(w.y, v[4 * q + 1], dot);
                dot = __fmaf_rn(w.z, v[4 * q + 2], dot);
                dot = __fmaf_rn(w.w, v[4 * q + 3], dot);
            }
            const float u = fmaxf(__fmaf_rn(-2.f, dot, __fadd_rn(s_d2[aa], s2)), 0.f);
            if (u < bestU) { bestU = u; bestI = tile0 + aa; }
        }
    }
    if (active) {
        out[n]            = t2s[bestI];
        out[Npix + n]     = b1s[bestI];
        out[2 * Npix + n] = __fsqrt_rn(bestU);
    }
}

// ---------------------------------------------------------------------------
extern "C" void kernel_launch(void* const* d_in, const int* in_sizes, int n_in,
                              void* d_out, int out_size) {
    const float* sig    = (const float*)d_in[0];
    const float* db_mag = (const float*)d_in[1];
    const float* t2s    = (const float*)d_in[2];
    const float* b1s    = (const float*)d_in[3];
    const float* delta  = (const float*)d_in[4];

    const int etl  = in_sizes[4];
    const int D    = in_sizes[1] / etl;
    const int Npix = in_sizes[0] / etl;
    float* out = (float*)d_out;

    const int P = (D + 1) / 2;
    const size_t dyn = (size_t)(P * 16 + 2 * P + NG * NPB) * 4 + (size_t)(NG * NPB) * 4;
    cudaFuncSetAttribute(match8_kernel,
                         cudaFuncAttributeMaxDynamicSharedMemorySize, (int)dyn);

    prep_kernel<<<32, 128>>>(delta, db_mag, D, etl);
    match16_kernel<<<(Npix + 255) / 256, 256>>>(sig, t2s, b1s, out, Npix, D, etl);
    match8_kernel<<<(Npix + NPB - 1) / NPB, THREADS, dyn>>>(sig, t2s, b1s, out,
                                                           Npix, D, etl);
}

// round 8
// speedup vs baseline: 14.3203x; 1.0395x over previous
#include <cuda_runtime.h>
#include <math.h>

// DictionaryMatchingTv — bit-replicated fp32 nearest-atom search.
// R8: single fused match kernel (K8 + K16 branches) to drop one ~4us graph
// node; proven R7 parallel prep + R3/R7 FFMA2 hot loop untouched.

#define MAX_D   4096
#define MAX_ETL 16
#define NPB     256   // pixels per block (K8 path)
#define NG      4     // dictionary chunks (K8 path)
#define THREADS 1024

typedef unsigned long long ull;

__device__ int   g_cols[MAX_ETL];
__device__ int   g_ncols, g_kpad;

// K=8 path: pair-interleaved dict (a0k,a1k per k), flat d2 per atom (padded)
__device__ float g_dbp[((MAX_D + 1) / 2) * 16];
__device__ float g_d2p[MAX_D + 1];

// K=16 fallback path
__device__ float g_db16[MAX_D * MAX_ETL];
__device__ float g_d2_16[MAX_D];

// ---- packed f32x2 helpers (per-lane IEEE rn, identical to scalar) --------
__device__ __forceinline__ ull pack2(float lo, float hi) {
    ull r; asm("mov.b64 %0, {%1, %2};" : "=l"(r) : "f"(lo), "f"(hi)); return r;
}
__device__ __forceinline__ void unpack2(ull v, float& lo, float& hi) {
    asm("mov.b64 {%0, %1}, %2;" : "=f"(lo), "=f"(hi) : "l"(v));
}
__device__ __forceinline__ ull ffma2(ull a, ull b, ull c) {
    ull d; asm("fma.rn.f32x2 %0, %1, %2, %3;" : "=l"(d) : "l"(a), "l"(b), "l"(c)); return d;
}
__device__ __forceinline__ ull fadd2(ull a, ull b) {
    ull d; asm("add.rn.f32x2 %0, %1, %2;" : "=l"(d) : "l"(a), "l"(b)); return d;
}

// ---------------------------------------------------------------------------
// Prep (R7-proven, fully parallel): mask + normalize + pair-interleave.
// ---------------------------------------------------------------------------
__global__ void __launch_bounds__(128)
prep_kernel(const float* __restrict__ delta, const float* __restrict__ db_mag,
            int D, int etl) {
    __shared__ int s_cols[MAX_ETL];
    __shared__ int s_ncols;
    if (threadIdx.x == 0) {
        int cnt = 0;
        for (int e = 0; e < etl && e < MAX_ETL; e++)
            if (__fmul_rn(delta[e], 1e-3f) < 1e-3f) s_cols[cnt++] = e;
        s_ncols = cnt;
        if (blockIdx.x == 0) {
            for (int k = 0; k < cnt; k++) g_cols[k] = s_cols[k];
            g_ncols = cnt;
            g_kpad  = (cnt <= 8) ? 8 : 16;
        }
    }
    __syncthreads();
    const int ncols = s_ncols;
    const int kp    = (ncols <= 8) ? 8 : 16;
    const int Dpad  = (D + 1) & ~1;

    for (int a = blockIdx.x * blockDim.x + threadIdx.x; a < Dpad;
         a += gridDim.x * blockDim.x) {
        const int d = (a < D) ? a : D - 1;          // pad = duplicate last atom
        float x[MAX_ETL];
#pragma unroll
        for (int k = 0; k < MAX_ETL; k++)
            x[k] = (k < ncols) ? db_mag[d * etl + s_cols[k]] : 0.f;
        float ss = 0.f;
#pragma unroll
        for (int k = 0; k < MAX_ETL; k++) ss = __fadd_rn(ss, __fmul_rn(x[k], x[k]));
        const float nn = __fsqrt_rn(ss);
        float v[MAX_ETL]; float d2 = 0.f;
#pragma unroll
        for (int k = 0; k < MAX_ETL; k++) {
            v[k] = (nn > 0.f) ? __fdiv_rn(x[k], nn) : 0.f;
            d2 = __fadd_rn(d2, __fmul_rn(v[k], v[k]));
        }
        if (kp == 8) {
            const int base = (a >> 1) * 16 + (a & 1);
#pragma unroll
            for (int k = 0; k < 8; k++) g_dbp[base + 2 * k] = v[k];
            g_d2p[a] = d2;
        } else if (a < D) {
#pragma unroll
            for (int k = 0; k < MAX_ETL; k++) g_db16[d * MAX_ETL + k] = v[k];
            g_d2_16[d] = d2;
        }
    }
}

// ---------------------------------------------------------------------------
// Signal prep (two-stage normalization, exact fp32 replication).
// ---------------------------------------------------------------------------
template <int K>
__device__ __forceinline__ void prep_signal(const float* __restrict__ sig,
                                            int n, bool active, int etl,
                                            const int* s_cols, int ncols,
                                            float* v, float& s2) {
    float raw[MAX_ETL];
#pragma unroll
    for (int e = 0; e < MAX_ETL; e++)
        raw[e] = (active && e < etl) ? sig[n * etl + e] : 0.f;
    float ss1 = 0.f;
#pragma unroll
    for (int e = 0; e < MAX_ETL; e++) ss1 = __fadd_rn(ss1, __fmul_rn(raw[e], raw[e]));
    const float n1 = __fsqrt_rn(ss1);
    float t[K];
#pragma unroll
    for (int k = 0; k < K; k++) {
        t[k] = 0.f;
        if (k < ncols) t[k] = (n1 > 0.f) ? __fdiv_rn(raw[s_cols[k]], n1) : 0.f;
    }
    float ss2 = 0.f;
#pragma unroll
    for (int k = 0; k < K; k++) ss2 = __fadd_rn(ss2, __fmul_rn(t[k], t[k]));
    const float n2 = __fsqrt_rn(ss2);
#pragma unroll
    for (int k = 0; k < K; k++) v[k] = (n2 > 0.f) ? __fdiv_rn(t[k], n2) : 0.f;
    s2 = 0.f;
#pragma unroll
    for (int k = 0; k < K; k++) s2 = __fadd_rn(s2, __fmul_rn(v[k], v[k]));
}

// ---------------------------------------------------------------------------
// Fused worker: one launch, internal K8/K16 dispatch.
// ---------------------------------------------------------------------------
__global__ void __launch_bounds__(THREADS, 1)
match_kernel(const float* __restrict__ sig,
             const float* __restrict__ t2s,
             const float* __restrict__ b1s,
             float* __restrict__ out,
             int Npix, int D, int etl) {
    extern __shared__ char smem_raw[];
    __shared__ int s_cols[MAX_ETL];
    __shared__ int s_ncols;

    const int tid = threadIdx.x;
    if (tid < MAX_ETL) s_cols[tid] = g_cols[tid];
    if (tid == 0) s_ncols = g_ncols;

    if (g_kpad == 8) {
        // ================= K8 path (R3/R7-exact hot loop) =================
        const int P = (D + 1) >> 1;             // atom pairs (padded)
        float* s_db = (float*)smem_raw;         // P*16 floats, pair-interleaved
        float* s_d2 = s_db + P * 16;            // 2*P floats
        float* s_bu = s_d2 + 2 * P;
        int*   s_bi = (int*)(s_bu + NG * NPB);

        const int px  = tid & (NPB - 1);
        const int grp = tid >> 8;               // 0..3

        {
            const float4* src = (const float4*)g_dbp;
            float4* dst = (float4*)s_db;
            for (int i = tid; i < P * 4; i += THREADS) dst[i] = src[i];
            for (int i = tid; i < 2 * P; i += THREADS) s_d2[i] = g_d2p[i];
        }
        __syncthreads();

        const int n = blockIdx.x * NPB + px;
        const bool active = (n < Npix);

        float v[8]; float s2;
        prep_signal<8>(sig, n, active, etl, s_cols, s_ncols, v, s2);
        ull vk2[8];
#pragma unroll
        for (int k = 0; k < 8; k++) vk2[k] = pack2(v[k], v[k]);
        const ull s2p  = pack2(s2, s2);
        const ull neg2 = pack2(-2.f, -2.f);
        __syncthreads();

        const int Lp   = (P + NG - 1) / NG;
        const int myp0 = grp * Lp;
        const int myp1 = min(myp0 + Lp, P);

        float bU = INFINITY;
        int   bA = 0;

        const ull* pp = (const ull*)s_db + (size_t)myp0 * 8;
#pragma unroll 2
        for (int p = myp0; p < myp1; p++, pp += 8) {
            ull acc = 0ull;
#pragma unroll
            for (int k = 0; k < 8; k++) acc = ffma2(pp[k], vk2[k], acc);
            const ull d2pair = *(const ull*)&s_d2[2 * p];
            const ull h  = fadd2(d2pair, s2p);
            const ull u2 = ffma2(neg2, acc, h);     // exact: 2*dot unrounded
            float u0, u1; unpack2(u2, u0, u1);
            u0 = fmaxf(u0, 0.f);
            u1 = fmaxf(u1, 0.f);
            if (u0 < bU) { bU = u0; bA = 2 * p; }   // strict < -> first min
            if (u1 < bU) { bU = u1; bA = 2 * p + 1; }
        }
        if (bA >= D) bA = D - 1;                    // pad lane = dup of last

        s_bu[grp * NPB + px] = bU;
        s_bi[grp * NPB + px] = bA;
        __syncthreads();

        if (grp == 0 && active) {
            float bu = s_bu[px]; int bi = s_bi[px];
#pragma unroll
            for (int g = 1; g < NG; g++) {
                const float u = s_bu[g * NPB + px];
                const int   i = s_bi[g * NPB + px];
                if (u < bu || (u == bu && i < bi)) { bu = u; bi = i; }
            }
            out[n]            = t2s[bi];
            out[Npix + n]     = b1s[bi];
            out[2 * Npix + n] = __fsqrt_rn(bu);
        }
    } else {
        // ================= K16 fallback (tiled, 1024 threads) =============
        constexpr int K = 16, TS = 512;
        float* s_db = (float*)smem_raw;          // TS*K floats
        float* s_d2 = s_db + TS * K;             // TS floats
        __syncthreads();                         // s_cols ready

        const int n = blockIdx.x * THREADS + tid;
        const bool active = (n < Npix);

        float v[K]; float s2;
        prep_signal<K>(sig, n, active, etl, s_cols, s_ncols, v, s2);

        float bestU = INFINITY; int bestI = 0;
        for (int tile0 = 0; tile0 < D; tile0 += TS) {
            const int cnt = min(TS, D - tile0);
            __syncthreads();
            const float4* src = (const float4*)&g_db16[tile0 * K];
            float4* dst = (float4*)s_db;
            for (int idx = tid; idx < cnt * K / 4; idx += THREADS) dst[idx] = src[idx];
            for (int idx = tid; idx < cnt; idx += THREADS) s_d2[idx] = g_d2_16[tile0 + idx];
            __syncthreads();
            for (int aa = 0; aa < cnt; aa++) {
                const float4* p = (const float4*)&s_db[aa * K];
                float dot = 0.f;
#pragma unroll
                for (int q = 0; q < K / 4; q++) {
                    float4 w = p[q];
                    dot = __fmaf_rn(w.x, v[4 * q + 0], dot);
                    dot = __fmaf_rn(w.y, v[4 * q + 1], dot);
                    dot = __fmaf_rn(w.z, v[4 * q + 2], dot);
                    dot = __fmaf_rn(w.w, v[4 * q + 3], dot);
                }
                const float u = fmaxf(__fmaf_rn(-2.f, dot, __fadd_rn(s_d2[aa], s2)), 0.f);
                if (u < bestU) { bestU = u; bestI = tile0 + aa; }
            }
        }
        if (active) {
            out[n]            = t2s[bestI];
            out[Npix + n]     = b1s[bestI];
            out[2 * Npix + n] = __fsqrt_rn(bestU);
        }
    }
}

// ---------------------------------------------------------------------------
extern "C" void kernel_launch(void* const* d_in, const int* in_sizes, int n_in,
                              void* d_out, int out_size) {
    const float* sig    = (const float*)d_in[0];
    const float* db_mag = (const float*)d_in[1];
    const float* t2s    = (const float*)d_in[2];
    const float* b1s    = (const float*)d_in[3];
    const float* delta  = (const float*)d_in[4];

    const int etl  = in_sizes[4];
    const int D    = in_sizes[1] / etl;
    const int Npix = in_sizes[0] / etl;
    float* out = (float*)d_out;

    // dynamic smem: max of K8 layout and K16 tile layout
    const int P = (D + 1) / 2;
    const size_t dyn8  = (size_t)(P * 16 + 2 * P + NG * NPB) * 4
                       + (size_t)(NG * NPB) * 4;
    const size_t dyn16 = (size_t)(512 * 16 + 512) * 4;
    const size_t dyn   = (dyn8 > dyn16) ? dyn8 : dyn16;
    cudaFuncSetAttribute(match_kernel,
                         cudaFuncAttributeMaxDynamicSharedMemorySize, (int)dyn);

    // grid sized for the K8 path (NPB pixels/block); covers K16 path too
    // (K16 uses THREADS pixels/block, needing fewer blocks).
    const int grid = (Npix + NPB - 1) / NPB;
    prep_kernel<<<32, 128>>>(delta, db_mag, D, etl);
    match_kernel<<<grid, THREADS, dyn>>>(sig, t2s, b1s, out, Npix, D, etl);
}